// round 13
// baseline (speedup 1.0000x reference)
#include <cuda_runtime.h>
#include <cstdint>

#define BB 32
#define CC 448
#define HWI 32
#define PIN 1024       // 32*32
#define HWF 64
#define NPOS 4096
#define DP 100
#define DPAD 104
#define OHW 256

__device__ __forceinline__ void mbar_init(unsigned int mbar, unsigned int cnt) {
    asm volatile("mbarrier.init.shared.b64 [%0], %1;" :: "r"(mbar), "r"(cnt) : "memory");
}
__device__ __forceinline__ void mbar_expect_tx(unsigned int mbar, unsigned int bytes) {
    asm volatile("mbarrier.arrive.expect_tx.shared.b64 _, [%0], %1;"
                 :: "r"(mbar), "r"(bytes) : "memory");
}
__device__ __forceinline__ void bulk_g2s(unsigned int sdst, const void* gsrc,
                                         unsigned int bytes, unsigned int mbar) {
    asm volatile("cp.async.bulk.shared::cta.global.mbarrier::complete_tx::bytes "
                 "[%0], [%1], %2, [%3];"
                 :: "r"(sdst), "l"(gsrc), "r"(bytes), "r"(mbar) : "memory");
}
__device__ __forceinline__ void mbar_wait(unsigned int mbar, unsigned int parity) {
    asm volatile(
        "{\n\t.reg .pred P;\n\t"
        "WAIT_%=:\n\t"
        "mbarrier.try_wait.parity.acquire.cta.shared::cta.b64 P, [%0], %1, 0x989680;\n\t"
        "@P bra.uni DONE_%=;\n\t"
        "bra.uni WAIT_%=;\n\t"
        "DONE_%=:\n\t}"
        :: "r"(mbar), "r"(parity) : "memory");
}

// m16n8k8 tf32 MMA (A row-major, B col-major), accumulate in place.
__device__ __forceinline__ void mma8(float* d, const unsigned* a, const unsigned* b) {
    asm volatile(
        "mma.sync.aligned.m16n8k8.row.col.f32.tf32.tf32.f32 "
        "{%0,%1,%2,%3}, {%4,%5,%6,%7}, {%8,%9}, {%0,%1,%2,%3};"
        : "+f"(d[0]), "+f"(d[1]), "+f"(d[2]), "+f"(d[3])
        : "r"(a[0]), "r"(a[1]), "r"(a[2]), "r"(a[3]), "r"(b[0]), "r"(b[1]));
}

// ---- scratch (static device globals; no allocation) ----
__device__ float g_Whi[DPAD * CC];   // [d][c] tf32-hi, rows 100..103 zero
__device__ float g_Wlo[DPAD * CC];   // [d][c] residual
__device__ float g_meanT[NPOS * DP];
__device__ float g_proj[(size_t)BB * PIN * DP];
__device__ float g_dist[(size_t)BB * NPOS];

// ---------------------------------------------------------------------------
__global__ void prep_w_kernel(const float* __restrict__ W) {
    int i = blockIdx.x * blockDim.x + threadIdx.x;
    if (i < DPAD * CC) {
        int d = i / CC;
        float v = (d < DP) ? W[i] : 0.f;
        float hi = __uint_as_float(__float_as_uint(v) & 0xFFFFE000u);
        g_Whi[i] = hi;
        g_Wlo[i] = v - hi;
    }
}

// ---------------------------------------------------------------------------
__global__ void prep_mean_kernel(const float* __restrict__ mean) {
    __shared__ float t[32][33];
    const int n0 = blockIdx.x * 32, c0 = blockIdx.y * 32;
    const int tx = threadIdx.x, ty = threadIdx.y;
#pragma unroll
    for (int j = 0; j < 32; j += 8) {
        int c = c0 + ty + j;
        if (c < DP) t[ty + j][tx] = mean[(size_t)c * NPOS + n0 + tx];
    }
    __syncthreads();
    int c = c0 + tx;
    if (c < DP) {
#pragma unroll
        for (int j = 0; j < 32; j += 8) {
            int n = n0 + ty + j;
            g_meanT[(size_t)n * DP + c] = t[tx][ty + j];
        }
    }
}

// ---------------------------------------------------------------------------
// Tensor-core projection. Grid (16, 32), 256 threads = 8 warps.
// warp = (m-tile wm = w&3 -> p base wm*16, d-half wd = w>>2 -> n-tiles
// [7*wd, min(13, 7*wd+7))). Fragment mapping identical to proven R12.
// ---------------------------------------------------------------------------
__global__ __launch_bounds__(256) void proj_kernel(const float* __restrict__ X,
                                                   const float* __restrict__ bias) {
    __shared__ float Xs[32 * 72];        // [c][p] 9.2 KB
    __shared__ float Wh[DPAD * 36];      // [d][k] 15 KB
    __shared__ float Wl[DPAD * 36];      // 15 KB
    const int tid = threadIdx.x;
    const int w = tid >> 5, lane = tid & 31;
    const int g = lane >> 2, tig = lane & 3;
    const int wm = w & 3, wd = w >> 2;
    const int ploc = wm * 16;
    const int n0t = 7 * wd;
    const int n1t = (wd == 0) ? 7 : 13;
    const int ptile = blockIdx.x;
    const int b = blockIdx.y;

    float D[7][4];
#pragma unroll
    for (int n = 0; n < 7; n++)
#pragma unroll
        for (int q = 0; q < 4; q++) D[n][q] = 0.f;

    const float* Xb = X + ((size_t)b * CC) * PIN + ptile * 64;

    for (int c0 = 0; c0 < CC; c0 += 32) {
        for (int i = tid; i < 2048; i += 256) {
            int c = i >> 6, p = i & 63;
            Xs[c * 72 + p] = Xb[(size_t)(c0 + c) * PIN + p];
        }
        for (int i = tid; i < DPAD * 32; i += 256) {
            int d = i >> 5, k = i & 31;
            Wh[d * 36 + k] = g_Whi[d * CC + c0 + k];
            Wl[d * 36 + k] = g_Wlo[d * CC + c0 + k];
        }
        __syncthreads();

#pragma unroll
        for (int s = 0; s < 4; s++) {
            const int k0 = 8 * s;
            float ra[4];
            ra[0] = Xs[(k0 + tig) * 72 + ploc + g];
            ra[1] = Xs[(k0 + tig) * 72 + ploc + g + 8];
            ra[2] = Xs[(k0 + tig + 4) * 72 + ploc + g];
            ra[3] = Xs[(k0 + tig + 4) * 72 + ploc + g + 8];
            unsigned ah[4], al[4];
#pragma unroll
            for (int q = 0; q < 4; q++) {
                ah[q] = __float_as_uint(ra[q]) & 0xFFFFE000u;
                al[q] = __float_as_uint(ra[q] - __uint_as_float(ah[q]));
            }
            for (int n = n0t; n < n1t; n++) {
                const int dr = (8 * n + g) * 36 + k0 + tig;
                unsigned bh[2], bl[2];
                bh[0] = __float_as_uint(Wh[dr]);
                bh[1] = __float_as_uint(Wh[dr + 4]);
                bl[0] = __float_as_uint(Wl[dr]);
                bl[1] = __float_as_uint(Wl[dr + 4]);
                mma8(D[n - n0t], ah, bh);
                mma8(D[n - n0t], al, bh);
                mma8(D[n - n0t], ah, bl);
            }
        }
        __syncthreads();
    }

    const int prow = ptile * 64 + ploc + g;
    for (int n = n0t; n < n1t; n++) {
        const int db = 8 * n + 2 * tig;
        if (db < DP) {
            float b0 = bias[db], b1 = bias[db + 1];
            float* o0 = g_proj + ((size_t)b * PIN + prow) * DP + db;
            float* o1 = g_proj + ((size_t)b * PIN + prow + 8) * DP + db;
            const float* Dn = D[n - n0t];
            *(float2*)o0 = make_float2(Dn[0] + b0, Dn[1] + b1);
            *(float2*)o1 = make_float2(Dn[2] + b0, Dn[3] + b1);
        }
    }
}

// ---------------------------------------------------------------------------
// Tensor-core Mahalanobis. One block per n, 256 threads = 8 warps.
// j-tiles t = w, w+8. Fragment code identical to proven R11/R12.
// Dyn smem floats: ICs[0..10400) | DmT[10400..14560)   (58240 B)
// ---------------------------------------------------------------------------
extern __shared__ float s_mh[];
__global__ __launch_bounds__(256) void maha_kernel(const float* __restrict__ ic) {
    float* ICs = s_mh;                 // [104][100]
    float* DmT = s_mh + 10400;         // [104][40] (cols 0..31 used)
    __shared__ float dists[BB];
    __shared__ __align__(8) unsigned long long mbar_sto[5];

    const int n = blockIdx.x;
    const int tid = threadIdx.x;
    const int w = tid >> 5, lane = tid & 31;
    const int g = lane >> 2, tig = lane & 3;

    unsigned int mb0 = (unsigned int)__cvta_generic_to_shared(&mbar_sto[0]);
    unsigned int icsh = (unsigned int)__cvta_generic_to_shared(ICs);
    const float* icn = ic + (size_t)n * (DP * DP);

    if (tid == 0) {
#pragma unroll
        for (int k = 0; k < 5; k++) mbar_init(mb0 + 8 * k, 1);
        asm volatile("fence.proxy.async.shared::cta;" ::: "memory");
#pragma unroll
        for (int k = 0; k < 5; k++) {
            mbar_expect_tx(mb0 + 8 * k, 8000);
            bulk_g2s(icsh + k * 8000, icn + k * 2000, 8000, mb0 + 8 * k);
        }
    }

    for (int i = tid; i < 400; i += 256) ICs[10000 + i] = 0.f;
    if (w < 4) DmT[(100 + w) * 40 + lane] = 0.f;
    if (tid < BB) dists[tid] = 0.f;

    const int yo = n >> 6, xo = n & 63;
    float yin = (yo + 0.5f) * 0.5f - 0.5f;
    float xin = (xo + 0.5f) * 0.5f - 0.5f;
    int y0 = (int)floorf(yin), x0 = (int)floorf(xin);
    float fy = yin - (float)y0, fx = xin - (float)x0;
    int y0c = max(y0, 0), y1c = min(y0 + 1, HWI - 1);
    int x0c = max(x0, 0), x1c = min(x0 + 1, HWI - 1);
    float w00 = (1.f - fy) * (1.f - fx), w01 = (1.f - fy) * fx;
    float w10 = fy * (1.f - fx),         w11 = fy * fx;
    int p00 = y0c * HWI + x0c, p01 = y0c * HWI + x1c;
    int p10 = y1c * HWI + x0c, p11 = y1c * HWI + x1c;

    const float* mt = g_meanT + (size_t)n * DP;
    for (int idx = tid; idx < 800; idx += 256) {
        int b = idx / 25;
        int q = idx - b * 25;
        int c = q * 4;
        const float* P = g_proj + (size_t)b * PIN * DP;
        float4 t00 = *(const float4*)&P[p00 * DP + c];
        float4 t01 = *(const float4*)&P[p01 * DP + c];
        float4 t10 = *(const float4*)&P[p10 * DP + c];
        float4 t11 = *(const float4*)&P[p11 * DP + c];
        float4 m4 = *(const float4*)&mt[c];
        float v0 = w00 * t00.x + w01 * t01.x + w10 * t10.x + w11 * t11.x - m4.x;
        float v1 = w00 * t00.y + w01 * t01.y + w10 * t10.y + w11 * t11.y - m4.y;
        float v2 = w00 * t00.z + w01 * t01.z + w10 * t10.z + w11 * t11.z - m4.z;
        float v3 = w00 * t00.w + w01 * t01.w + w10 * t10.w + w11 * t11.w - m4.w;
        unsigned r0, r1, r2, r3;
        asm("cvt.rna.tf32.f32 %0, %1;" : "=r"(r0) : "f"(v0));
        asm("cvt.rna.tf32.f32 %0, %1;" : "=r"(r1) : "f"(v1));
        asm("cvt.rna.tf32.f32 %0, %1;" : "=r"(r2) : "f"(v2));
        asm("cvt.rna.tf32.f32 %0, %1;" : "=r"(r3) : "f"(v3));
        DmT[(c + 0) * 40 + b] = __uint_as_float(r0);
        DmT[(c + 1) * 40 + b] = __uint_as_float(r1);
        DmT[(c + 2) * 40 + b] = __uint_as_float(r2);
        DmT[(c + 3) * 40 + b] = __uint_as_float(r3);
    }
    __syncthreads();

    float accd[4] = {0.f, 0.f, 0.f, 0.f};
    int waited = -1;

    for (int t = w; t < 13; t += 8) {
        int need = (8 * t + 7) / 20;
        if (need > 4) need = 4;
        while (waited < need) { waited++; mbar_wait(mb0 + 8 * waited, 0); }
        const int j0 = 8 * t;

        float d0[4] = {0.f, 0.f, 0.f, 0.f};
        float d1[4] = {0.f, 0.f, 0.f, 0.f};
#pragma unroll
        for (int s = 0; s < 13; s++) {
            const int k0 = 8 * s;
            float braw0 = ICs[(j0 + g) * DP + k0 + tig];
            float braw1 = (s < 12) ? ICs[(j0 + g) * DP + k0 + tig + 4] : 0.f;
            unsigned bh[2], bl[2];
            bh[0] = __float_as_uint(braw0) & 0xFFFFE000u;
            bh[1] = __float_as_uint(braw1) & 0xFFFFE000u;
            bl[0] = __float_as_uint(braw0 - __uint_as_float(bh[0]));
            bl[1] = __float_as_uint(braw1 - __uint_as_float(bh[1]));
            unsigned a0[4], a1[4];
            a0[0] = __float_as_uint(DmT[(k0 + tig) * 40 + g]);
            a0[1] = __float_as_uint(DmT[(k0 + tig) * 40 + g + 8]);
            a0[2] = __float_as_uint(DmT[(k0 + tig + 4) * 40 + g]);
            a0[3] = __float_as_uint(DmT[(k0 + tig + 4) * 40 + g + 8]);
            a1[0] = __float_as_uint(DmT[(k0 + tig) * 40 + 16 + g]);
            a1[1] = __float_as_uint(DmT[(k0 + tig) * 40 + 24 + g]);
            a1[2] = __float_as_uint(DmT[(k0 + tig + 4) * 40 + 16 + g]);
            a1[3] = __float_as_uint(DmT[(k0 + tig + 4) * 40 + 24 + g]);
            mma8(d0, a0, bh);
            mma8(d0, a0, bl);
            mma8(d1, a1, bh);
            mma8(d1, a1, bl);
        }
        const float* wj0 = &DmT[(j0 + 2 * tig) * 40];
        const float* wj1 = &DmT[(j0 + 2 * tig + 1) * 40];
        accd[0] += d0[0] * wj0[g]      + d0[1] * wj1[g];
        accd[1] += d0[2] * wj0[g + 8]  + d0[3] * wj1[g + 8];
        accd[2] += d1[0] * wj0[16 + g] + d1[1] * wj1[16 + g];
        accd[3] += d1[2] * wj0[24 + g] + d1[3] * wj1[24 + g];
    }

    atomicAdd(&dists[g], accd[0]);
    atomicAdd(&dists[g + 8], accd[1]);
    atomicAdd(&dists[16 + g], accd[2]);
    atomicAdd(&dists[24 + g], accd[3]);
    __syncthreads();
    if (tid < BB) g_dist[(size_t)tid * NPOS + n] = dists[tid];
}

// ---------------------------------------------------------------------------
__global__ void upsample_kernel(const float* __restrict__ nmin_p,
                                const float* __restrict__ nmax_p,
                                float* __restrict__ out) {
    const int b = blockIdx.y;
    const int i = blockIdx.x * blockDim.x + threadIdx.x;
    const int yo = i >> 6;
    const int xb = (i & 63) * 4;

    float yin = (yo + 0.5f) * 0.25f - 0.5f;
    int y0 = (int)floorf(yin);
    float fy = yin - (float)y0;
    int y0c = max(y0, 0), y1c = min(y0 + 1, HWF - 1);

    const float* dn = g_dist + (size_t)b * NPOS;
    const float* r0 = dn + y0c * HWF;
    const float* r1 = dn + y1c * HWF;
    float nmin = *nmin_p, nmax = *nmax_p;
    float inv = 1.f / (nmax - nmin + 1e-8f);

    float4 res;
    float* resp = (float*)&res;
#pragma unroll
    for (int k = 0; k < 4; k++) {
        int xo = xb + k;
        float xin = (xo + 0.5f) * 0.25f - 0.5f;
        int x0 = (int)floorf(xin);
        float fx = xin - (float)x0;
        int x0c = max(x0, 0), x1c = min(x0 + 1, HWF - 1);
        float v = (1.f - fy) * ((1.f - fx) * r0[x0c] + fx * r0[x1c])
                + fy * ((1.f - fx) * r1[x0c] + fx * r1[x1c]);
        resp[k] = (v - nmin) * inv;
    }
    *(float4*)&out[(size_t)b * (OHW * OHW) + yo * OHW + xb] = res;
}

// ---------------------------------------------------------------------------
extern "C" void kernel_launch(void* const* d_in, const int* in_sizes, int n_in,
                              void* d_out, int out_size) {
    (void)in_sizes; (void)n_in; (void)out_size;
    const float* combined = (const float*)d_in[0];
    const float* proj_w   = (const float*)d_in[1];
    const float* proj_b   = (const float*)d_in[2];
    const float* mean     = (const float*)d_in[3];
    const float* inv_cov  = (const float*)d_in[4];
    const float* nmin     = (const float*)d_in[5];
    const float* nmax     = (const float*)d_in[6];
    float* out = (float*)d_out;

    static int smem_set = 0;
    if (!smem_set) {
        cudaFuncSetAttribute(maha_kernel,
                             cudaFuncAttributeMaxDynamicSharedMemorySize,
                             58240);
        smem_set = 1;
    }

    prep_w_kernel<<<(DPAD * CC + 255) / 256, 256>>>(proj_w);
    prep_mean_kernel<<<dim3(NPOS / 32, 4), dim3(32, 8)>>>(mean);
    proj_kernel<<<dim3(16, BB), 256>>>(combined, proj_b);
    maha_kernel<<<NPOS, 256, 58240>>>(inv_cov);
    upsample_kernel<<<dim3(OHW * OHW / (256 * 4), BB), 256>>>(nmin, nmax, out);
}

// round 14
// speedup vs baseline: 1.3923x; 1.3923x over previous
#include <cuda_runtime.h>
#include <cstdint>

#define BB 32
#define CC 448
#define HWI 32
#define PIN 1024       // 32*32
#define HWF 64
#define NPOS 4096
#define DP 100
#define DPAD 104
#define OHW 256

__device__ __forceinline__ void mbar_init(unsigned int mbar, unsigned int cnt) {
    asm volatile("mbarrier.init.shared.b64 [%0], %1;" :: "r"(mbar), "r"(cnt) : "memory");
}
__device__ __forceinline__ void mbar_expect_tx(unsigned int mbar, unsigned int bytes) {
    asm volatile("mbarrier.arrive.expect_tx.shared.b64 _, [%0], %1;"
                 :: "r"(mbar), "r"(bytes) : "memory");
}
__device__ __forceinline__ void bulk_g2s(unsigned int sdst, const void* gsrc,
                                         unsigned int bytes, unsigned int mbar) {
    asm volatile("cp.async.bulk.shared::cta.global.mbarrier::complete_tx::bytes "
                 "[%0], [%1], %2, [%3];"
                 :: "r"(sdst), "l"(gsrc), "r"(bytes), "r"(mbar) : "memory");
}
__device__ __forceinline__ void mbar_wait(unsigned int mbar, unsigned int parity) {
    asm volatile(
        "{\n\t.reg .pred P;\n\t"
        "WAIT_%=:\n\t"
        "mbarrier.try_wait.parity.acquire.cta.shared::cta.b64 P, [%0], %1, 0x989680;\n\t"
        "@P bra.uni DONE_%=;\n\t"
        "bra.uni WAIT_%=;\n\t"
        "DONE_%=:\n\t}"
        :: "r"(mbar), "r"(parity) : "memory");
}

// m16n8k8 tf32 MMA (A row-major, B col-major), accumulate in place.
__device__ __forceinline__ void mma8(float* d, const unsigned* a, const unsigned* b) {
    asm volatile(
        "mma.sync.aligned.m16n8k8.row.col.f32.tf32.tf32.f32 "
        "{%0,%1,%2,%3}, {%4,%5,%6,%7}, {%8,%9}, {%0,%1,%2,%3};"
        : "+f"(d[0]), "+f"(d[1]), "+f"(d[2]), "+f"(d[3])
        : "r"(a[0]), "r"(a[1]), "r"(a[2]), "r"(a[3]), "r"(b[0]), "r"(b[1]));
}

// ---- scratch (static device globals; no allocation) ----
__device__ float g_Whi[DPAD * CC];   // [d][c] tf32-hi, rows 100..103 zero
__device__ float g_Wlo[DPAD * CC];   // [d][c] residual
__device__ float g_meanT[NPOS * DP];
__device__ float g_proj[(size_t)BB * PIN * DP];
__device__ float g_dist[(size_t)BB * NPOS];

// ---------------------------------------------------------------------------
__global__ void prep_w_kernel(const float* __restrict__ W) {
    int i = blockIdx.x * blockDim.x + threadIdx.x;
    if (i < DPAD * CC) {
        int d = i / CC;
        float v = (d < DP) ? W[i] : 0.f;
        float hi = __uint_as_float(__float_as_uint(v) & 0xFFFFE000u);
        g_Whi[i] = hi;
        g_Wlo[i] = v - hi;
    }
}

// ---------------------------------------------------------------------------
__global__ void prep_mean_kernel(const float* __restrict__ mean) {
    __shared__ float t[32][33];
    const int n0 = blockIdx.x * 32, c0 = blockIdx.y * 32;
    const int tx = threadIdx.x, ty = threadIdx.y;
#pragma unroll
    for (int j = 0; j < 32; j += 8) {
        int c = c0 + ty + j;
        if (c < DP) t[ty + j][tx] = mean[(size_t)c * NPOS + n0 + tx];
    }
    __syncthreads();
    int c = c0 + tx;
    if (c < DP) {
#pragma unroll
        for (int j = 0; j < 32; j += 8) {
            int n = n0 + ty + j;
            g_meanT[(size_t)n * DP + c] = t[tx][ty + j];
        }
    }
}

// ---------------------------------------------------------------------------
// Tensor-core projection. Grid (16, 32), 256 threads = 8 warps.
// warp = (m-tile wm = w&3 -> p base wm*16, d-half wd = w>>2).
// n-loop: COMPILE-TIME 7 iterations (nn), runtime base only in addresses;
// D indexed by nn -> no local-memory spill. Tile 13 skipped by predicate.
// ---------------------------------------------------------------------------
__global__ __launch_bounds__(256) void proj_kernel(const float* __restrict__ X,
                                                   const float* __restrict__ bias) {
    __shared__ float Xs[32 * 72];        // [c][p] 9.2 KB
    __shared__ float Wh[DPAD * 36];      // [d][k] 15 KB
    __shared__ float Wl[DPAD * 36];      // 15 KB
    const int tid = threadIdx.x;
    const int w = tid >> 5, lane = tid & 31;
    const int g = lane >> 2, tig = lane & 3;
    const int wm = w & 3, wd = w >> 2;
    const int ploc = wm * 16;
    const int n0t = 7 * wd;              // 0 or 7
    const int ptile = blockIdx.x;
    const int b = blockIdx.y;

    float D[7][4];
#pragma unroll
    for (int n = 0; n < 7; n++)
#pragma unroll
        for (int q = 0; q < 4; q++) D[n][q] = 0.f;

    const float* Xb = X + ((size_t)b * CC) * PIN + ptile * 64;

    for (int c0 = 0; c0 < CC; c0 += 32) {
        for (int i = tid; i < 2048; i += 256) {
            int c = i >> 6, p = i & 63;
            Xs[c * 72 + p] = Xb[(size_t)(c0 + c) * PIN + p];
        }
        for (int i = tid; i < DPAD * 32; i += 256) {
            int d = i >> 5, k = i & 31;
            Wh[d * 36 + k] = g_Whi[d * CC + c0 + k];
            Wl[d * 36 + k] = g_Wlo[d * CC + c0 + k];
        }
        __syncthreads();

#pragma unroll
        for (int s = 0; s < 4; s++) {
            const int k0 = 8 * s;
            float ra[4];
            ra[0] = Xs[(k0 + tig) * 72 + ploc + g];
            ra[1] = Xs[(k0 + tig) * 72 + ploc + g + 8];
            ra[2] = Xs[(k0 + tig + 4) * 72 + ploc + g];
            ra[3] = Xs[(k0 + tig + 4) * 72 + ploc + g + 8];
            unsigned ah[4], al[4];
#pragma unroll
            for (int q = 0; q < 4; q++) {
                ah[q] = __float_as_uint(ra[q]) & 0xFFFFE000u;
                al[q] = __float_as_uint(ra[q] - __uint_as_float(ah[q]));
            }
#pragma unroll
            for (int nn = 0; nn < 7; nn++) {
                if (wd == 1 && nn == 6) continue;   // tile 13 doesn't exist
                const int n = n0t + nn;
                const int dr = (8 * n + g) * 36 + k0 + tig;
                unsigned bh[2], bl[2];
                bh[0] = __float_as_uint(Wh[dr]);
                bh[1] = __float_as_uint(Wh[dr + 4]);
                bl[0] = __float_as_uint(Wl[dr]);
                bl[1] = __float_as_uint(Wl[dr + 4]);
                mma8(D[nn], ah, bh);
                mma8(D[nn], al, bh);
                mma8(D[nn], ah, bl);
            }
        }
        __syncthreads();
    }

    const int prow = ptile * 64 + ploc + g;
#pragma unroll
    for (int nn = 0; nn < 7; nn++) {
        if (wd == 1 && nn == 6) continue;
        const int n = n0t + nn;
        const int db = 8 * n + 2 * tig;
        if (db < DP) {
            float b0 = bias[db], b1 = bias[db + 1];
            float* o0 = g_proj + ((size_t)b * PIN + prow) * DP + db;
            float* o1 = g_proj + ((size_t)b * PIN + prow + 8) * DP + db;
            *(float2*)o0 = make_float2(D[nn][0] + b0, D[nn][1] + b1);
            *(float2*)o1 = make_float2(D[nn][2] + b0, D[nn][3] + b1);
        }
    }
}

// ---------------------------------------------------------------------------
// Tensor-core Mahalanobis (R11/R12-proven). One block per n, 128 thr.
// Dyn smem floats: ICs[0..10400) | DmT[10400..14560)   (58240 B)
// ---------------------------------------------------------------------------
extern __shared__ float s_mh[];
__global__ __launch_bounds__(128) void maha_kernel(const float* __restrict__ ic) {
    float* ICs = s_mh;                 // [104][100]
    float* DmT = s_mh + 10400;         // [104][40] (cols 0..31 used)
    __shared__ float dists[BB];
    __shared__ __align__(8) unsigned long long mbar_sto[5];

    const int n = blockIdx.x;
    const int tid = threadIdx.x;
    const int w = tid >> 5, lane = tid & 31;
    const int g = lane >> 2, tig = lane & 3;

    unsigned int mb0 = (unsigned int)__cvta_generic_to_shared(&mbar_sto[0]);
    unsigned int icsh = (unsigned int)__cvta_generic_to_shared(ICs);
    const float* icn = ic + (size_t)n * (DP * DP);

    if (tid == 0) {
#pragma unroll
        for (int k = 0; k < 5; k++) mbar_init(mb0 + 8 * k, 1);
        asm volatile("fence.proxy.async.shared::cta;" ::: "memory");
#pragma unroll
        for (int k = 0; k < 5; k++) {
            mbar_expect_tx(mb0 + 8 * k, 8000);
            bulk_g2s(icsh + k * 8000, icn + k * 2000, 8000, mb0 + 8 * k);
        }
    }

    for (int i = tid; i < 400; i += 128) ICs[10000 + i] = 0.f;
    DmT[(100 + (tid >> 5)) * 40 + (tid & 31)] = 0.f;
    if (tid < BB) dists[tid] = 0.f;

    const int yo = n >> 6, xo = n & 63;
    float yin = (yo + 0.5f) * 0.5f - 0.5f;
    float xin = (xo + 0.5f) * 0.5f - 0.5f;
    int y0 = (int)floorf(yin), x0 = (int)floorf(xin);
    float fy = yin - (float)y0, fx = xin - (float)x0;
    int y0c = max(y0, 0), y1c = min(y0 + 1, HWI - 1);
    int x0c = max(x0, 0), x1c = min(x0 + 1, HWI - 1);
    float w00 = (1.f - fy) * (1.f - fx), w01 = (1.f - fy) * fx;
    float w10 = fy * (1.f - fx),         w11 = fy * fx;
    int p00 = y0c * HWI + x0c, p01 = y0c * HWI + x1c;
    int p10 = y1c * HWI + x0c, p11 = y1c * HWI + x1c;

    const float* mt = g_meanT + (size_t)n * DP;
    for (int idx = tid; idx < 800; idx += 128) {
        int b = idx / 25;
        int q = idx - b * 25;
        int c = q * 4;
        const float* P = g_proj + (size_t)b * PIN * DP;
        float4 t00 = *(const float4*)&P[p00 * DP + c];
        float4 t01 = *(const float4*)&P[p01 * DP + c];
        float4 t10 = *(const float4*)&P[p10 * DP + c];
        float4 t11 = *(const float4*)&P[p11 * DP + c];
        float4 m4 = *(const float4*)&mt[c];
        float v0 = w00 * t00.x + w01 * t01.x + w10 * t10.x + w11 * t11.x - m4.x;
        float v1 = w00 * t00.y + w01 * t01.y + w10 * t10.y + w11 * t11.y - m4.y;
        float v2 = w00 * t00.z + w01 * t01.z + w10 * t10.z + w11 * t11.z - m4.z;
        float v3 = w00 * t00.w + w01 * t01.w + w10 * t10.w + w11 * t11.w - m4.w;
        unsigned r0, r1, r2, r3;
        asm("cvt.rna.tf32.f32 %0, %1;" : "=r"(r0) : "f"(v0));
        asm("cvt.rna.tf32.f32 %0, %1;" : "=r"(r1) : "f"(v1));
        asm("cvt.rna.tf32.f32 %0, %1;" : "=r"(r2) : "f"(v2));
        asm("cvt.rna.tf32.f32 %0, %1;" : "=r"(r3) : "f"(v3));
        DmT[(c + 0) * 40 + b] = __uint_as_float(r0);
        DmT[(c + 1) * 40 + b] = __uint_as_float(r1);
        DmT[(c + 2) * 40 + b] = __uint_as_float(r2);
        DmT[(c + 3) * 40 + b] = __uint_as_float(r3);
    }
    __syncthreads();

    float accd[4] = {0.f, 0.f, 0.f, 0.f};
    int waited = -1;

    for (int t = w; t < 13; t += 4) {
        int need = (8 * t + 7) / 20;
        if (need > 4) need = 4;
        while (waited < need) { waited++; mbar_wait(mb0 + 8 * waited, 0); }
        const int j0 = 8 * t;

        float d0[4] = {0.f, 0.f, 0.f, 0.f};
        float d1[4] = {0.f, 0.f, 0.f, 0.f};
#pragma unroll
        for (int s = 0; s < 13; s++) {
            const int k0 = 8 * s;
            float braw0 = ICs[(j0 + g) * DP + k0 + tig];
            float braw1 = (s < 12) ? ICs[(j0 + g) * DP + k0 + tig + 4] : 0.f;
            unsigned bh[2], bl[2];
            bh[0] = __float_as_uint(braw0) & 0xFFFFE000u;
            bh[1] = __float_as_uint(braw1) & 0xFFFFE000u;
            bl[0] = __float_as_uint(braw0 - __uint_as_float(bh[0]));
            bl[1] = __float_as_uint(braw1 - __uint_as_float(bh[1]));
            unsigned a0[4], a1[4];
            a0[0] = __float_as_uint(DmT[(k0 + tig) * 40 + g]);
            a0[1] = __float_as_uint(DmT[(k0 + tig) * 40 + g + 8]);
            a0[2] = __float_as_uint(DmT[(k0 + tig + 4) * 40 + g]);
            a0[3] = __float_as_uint(DmT[(k0 + tig + 4) * 40 + g + 8]);
            a1[0] = __float_as_uint(DmT[(k0 + tig) * 40 + 16 + g]);
            a1[1] = __float_as_uint(DmT[(k0 + tig) * 40 + 24 + g]);
            a1[2] = __float_as_uint(DmT[(k0 + tig + 4) * 40 + 16 + g]);
            a1[3] = __float_as_uint(DmT[(k0 + tig + 4) * 40 + 24 + g]);
            mma8(d0, a0, bh);
            mma8(d0, a0, bl);
            mma8(d1, a1, bh);
            mma8(d1, a1, bl);
        }
        const float* wj0 = &DmT[(j0 + 2 * tig) * 40];
        const float* wj1 = &DmT[(j0 + 2 * tig + 1) * 40];
        accd[0] += d0[0] * wj0[g]      + d0[1] * wj1[g];
        accd[1] += d0[2] * wj0[g + 8]  + d0[3] * wj1[g + 8];
        accd[2] += d1[0] * wj0[16 + g] + d1[1] * wj1[16 + g];
        accd[3] += d1[2] * wj0[24 + g] + d1[3] * wj1[24 + g];
    }

    atomicAdd(&dists[g], accd[0]);
    atomicAdd(&dists[g + 8], accd[1]);
    atomicAdd(&dists[16 + g], accd[2]);
    atomicAdd(&dists[24 + g], accd[3]);
    __syncthreads();
    if (tid < BB) g_dist[(size_t)tid * NPOS + n] = dists[tid];
}

// ---------------------------------------------------------------------------
__global__ void upsample_kernel(const float* __restrict__ nmin_p,
                                const float* __restrict__ nmax_p,
                                float* __restrict__ out) {
    const int b = blockIdx.y;
    const int i = blockIdx.x * blockDim.x + threadIdx.x;
    const int yo = i >> 6;
    const int xb = (i & 63) * 4;

    float yin = (yo + 0.5f) * 0.25f - 0.5f;
    int y0 = (int)floorf(yin);
    float fy = yin - (float)y0;
    int y0c = max(y0, 0), y1c = min(y0 + 1, HWF - 1);

    const float* dn = g_dist + (size_t)b * NPOS;
    const float* r0 = dn + y0c * HWF;
    const float* r1 = dn + y1c * HWF;
    float nmin = *nmin_p, nmax = *nmax_p;
    float inv = 1.f / (nmax - nmin + 1e-8f);

    float4 res;
    float* resp = (float*)&res;
#pragma unroll
    for (int k = 0; k < 4; k++) {
        int xo = xb + k;
        float xin = (xo + 0.5f) * 0.25f - 0.5f;
        int x0 = (int)floorf(xin);
        float fx = xin - (float)x0;
        int x0c = max(x0, 0), x1c = min(x0 + 1, HWF - 1);
        float v = (1.f - fy) * ((1.f - fx) * r0[x0c] + fx * r0[x1c])
                + fy * ((1.f - fx) * r1[x0c] + fx * r1[x1c]);
        resp[k] = (v - nmin) * inv;
    }
    *(float4*)&out[(size_t)b * (OHW * OHW) + yo * OHW + xb] = res;
}

// ---------------------------------------------------------------------------
extern "C" void kernel_launch(void* const* d_in, const int* in_sizes, int n_in,
                              void* d_out, int out_size) {
    (void)in_sizes; (void)n_in; (void)out_size;
    const float* combined = (const float*)d_in[0];
    const float* proj_w   = (const float*)d_in[1];
    const float* proj_b   = (const float*)d_in[2];
    const float* mean     = (const float*)d_in[3];
    const float* inv_cov  = (const float*)d_in[4];
    const float* nmin     = (const float*)d_in[5];
    const float* nmax     = (const float*)d_in[6];
    float* out = (float*)d_out;

    static int smem_set = 0;
    if (!smem_set) {
        cudaFuncSetAttribute(maha_kernel,
                             cudaFuncAttributeMaxDynamicSharedMemorySize,
                             58240);
        smem_set = 1;
    }

    prep_w_kernel<<<(DPAD * CC + 255) / 256, 256>>>(proj_w);
    prep_mean_kernel<<<dim3(NPOS / 32, 4), dim3(32, 8)>>>(mean);
    proj_kernel<<<dim3(16, BB), 256>>>(combined, proj_b);
    maha_kernel<<<NPOS, 128, 58240>>>(inv_cov);
    upsample_kernel<<<dim3(OHW * OHW / (256 * 4), BB), 256>>>(nmin, nmax, out);
}

// round 15
// speedup vs baseline: 1.4603x; 1.0488x over previous
#include <cuda_runtime.h>
#include <cstdint>

#define BB 32
#define CC 448
#define HWI 32
#define PIN 1024       // 32*32
#define HWF 64
#define NPOS 4096
#define DP 100
#define DPAD 104
#define OHW 256

__device__ __forceinline__ void mbar_init(unsigned int mbar, unsigned int cnt) {
    asm volatile("mbarrier.init.shared.b64 [%0], %1;" :: "r"(mbar), "r"(cnt) : "memory");
}
__device__ __forceinline__ void mbar_expect_tx(unsigned int mbar, unsigned int bytes) {
    asm volatile("mbarrier.arrive.expect_tx.shared.b64 _, [%0], %1;"
                 :: "r"(mbar), "r"(bytes) : "memory");
}
__device__ __forceinline__ void bulk_g2s(unsigned int sdst, const void* gsrc,
                                         unsigned int bytes, unsigned int mbar) {
    asm volatile("cp.async.bulk.shared::cta.global.mbarrier::complete_tx::bytes "
                 "[%0], [%1], %2, [%3];"
                 :: "r"(sdst), "l"(gsrc), "r"(bytes), "r"(mbar) : "memory");
}
__device__ __forceinline__ void mbar_wait(unsigned int mbar, unsigned int parity) {
    asm volatile(
        "{\n\t.reg .pred P;\n\t"
        "WAIT_%=:\n\t"
        "mbarrier.try_wait.parity.acquire.cta.shared::cta.b64 P, [%0], %1, 0x989680;\n\t"
        "@P bra.uni DONE_%=;\n\t"
        "bra.uni WAIT_%=;\n\t"
        "DONE_%=:\n\t}"
        :: "r"(mbar), "r"(parity) : "memory");
}

// m16n8k8 tf32 MMA (A row-major, B col-major), accumulate in place.
__device__ __forceinline__ void mma8(float* d, const unsigned* a, const unsigned* b) {
    asm volatile(
        "mma.sync.aligned.m16n8k8.row.col.f32.tf32.tf32.f32 "
        "{%0,%1,%2,%3}, {%4,%5,%6,%7}, {%8,%9}, {%0,%1,%2,%3};"
        : "+f"(d[0]), "+f"(d[1]), "+f"(d[2]), "+f"(d[3])
        : "r"(a[0]), "r"(a[1]), "r"(a[2]), "r"(a[3]), "r"(b[0]), "r"(b[1]));
}

// ---- scratch (static device globals; no allocation) ----
__device__ float g_Whi[DPAD * CC];   // [d][c] tf32-hi, rows 100..103 zero
__device__ float g_Wlo[DPAD * CC];   // [d][c] residual
__device__ float g_meanT[NPOS * DP];
__device__ float g_proj[(size_t)BB * PIN * DP];
__device__ float g_dist[(size_t)BB * NPOS];

// ---------------------------------------------------------------------------
__global__ void prep_w_kernel(const float* __restrict__ W) {
    int i = blockIdx.x * blockDim.x + threadIdx.x;
    if (i < DPAD * CC) {
        int d = i / CC;
        float v = (d < DP) ? W[i] : 0.f;
        float hi = __uint_as_float(__float_as_uint(v) & 0xFFFFE000u);
        g_Whi[i] = hi;
        g_Wlo[i] = v - hi;
    }
}

// ---------------------------------------------------------------------------
__global__ void prep_mean_kernel(const float* __restrict__ mean) {
    __shared__ float t[32][33];
    const int n0 = blockIdx.x * 32, c0 = blockIdx.y * 32;
    const int tx = threadIdx.x, ty = threadIdx.y;
#pragma unroll
    for (int j = 0; j < 32; j += 8) {
        int c = c0 + ty + j;
        if (c < DP) t[ty + j][tx] = mean[(size_t)c * NPOS + n0 + tx];
    }
    __syncthreads();
    int c = c0 + tx;
    if (c < DP) {
#pragma unroll
        for (int j = 0; j < 32; j += 8) {
            int n = n0 + ty + j;
            g_meanT[(size_t)n * DP + c] = t[tx][ty + j];
        }
    }
}

// ---------------------------------------------------------------------------
// Tensor-core projection (R14-proven). Grid (16, 32), 256 threads = 8 warps.
// ---------------------------------------------------------------------------
__global__ __launch_bounds__(256) void proj_kernel(const float* __restrict__ X,
                                                   const float* __restrict__ bias) {
    __shared__ float Xs[32 * 72];        // [c][p] 9.2 KB
    __shared__ float Wh[DPAD * 36];      // [d][k] 15 KB
    __shared__ float Wl[DPAD * 36];      // 15 KB
    const int tid = threadIdx.x;
    const int w = tid >> 5, lane = tid & 31;
    const int g = lane >> 2, tig = lane & 3;
    const int wm = w & 3, wd = w >> 2;
    const int ploc = wm * 16;
    const int n0t = 7 * wd;              // 0 or 7
    const int ptile = blockIdx.x;
    const int b = blockIdx.y;

    float D[7][4];
#pragma unroll
    for (int n = 0; n < 7; n++)
#pragma unroll
        for (int q = 0; q < 4; q++) D[n][q] = 0.f;

    const float* Xb = X + ((size_t)b * CC) * PIN + ptile * 64;

    for (int c0 = 0; c0 < CC; c0 += 32) {
        for (int i = tid; i < 2048; i += 256) {
            int c = i >> 6, p = i & 63;
            Xs[c * 72 + p] = Xb[(size_t)(c0 + c) * PIN + p];
        }
        for (int i = tid; i < DPAD * 32; i += 256) {
            int d = i >> 5, k = i & 31;
            Wh[d * 36 + k] = g_Whi[d * CC + c0 + k];
            Wl[d * 36 + k] = g_Wlo[d * CC + c0 + k];
        }
        __syncthreads();

#pragma unroll
        for (int s = 0; s < 4; s++) {
            const int k0 = 8 * s;
            float ra[4];
            ra[0] = Xs[(k0 + tig) * 72 + ploc + g];
            ra[1] = Xs[(k0 + tig) * 72 + ploc + g + 8];
            ra[2] = Xs[(k0 + tig + 4) * 72 + ploc + g];
            ra[3] = Xs[(k0 + tig + 4) * 72 + ploc + g + 8];
            unsigned ah[4], al[4];
#pragma unroll
            for (int q = 0; q < 4; q++) {
                ah[q] = __float_as_uint(ra[q]) & 0xFFFFE000u;
                al[q] = __float_as_uint(ra[q] - __uint_as_float(ah[q]));
            }
#pragma unroll
            for (int nn = 0; nn < 7; nn++) {
                if (wd == 1 && nn == 6) continue;   // tile 13 doesn't exist
                const int n = n0t + nn;
                const int dr = (8 * n + g) * 36 + k0 + tig;
                unsigned bh[2], bl[2];
                bh[0] = __float_as_uint(Wh[dr]);
                bh[1] = __float_as_uint(Wh[dr + 4]);
                bl[0] = __float_as_uint(Wl[dr]);
                bl[1] = __float_as_uint(Wl[dr + 4]);
                mma8(D[nn], ah, bh);
                mma8(D[nn], al, bh);
                mma8(D[nn], ah, bl);
            }
        }
        __syncthreads();
    }

    const int prow = ptile * 64 + ploc + g;
#pragma unroll
    for (int nn = 0; nn < 7; nn++) {
        if (wd == 1 && nn == 6) continue;
        const int n = n0t + nn;
        const int db = 8 * n + 2 * tig;
        if (db < DP) {
            float b0 = bias[db], b1 = bias[db + 1];
            float* o0 = g_proj + ((size_t)b * PIN + prow) * DP + db;
            float* o1 = g_proj + ((size_t)b * PIN + prow + 8) * DP + db;
            *(float2*)o0 = make_float2(D[nn][0] + b0, D[nn][1] + b1);
            *(float2*)o1 = make_float2(D[nn][2] + b0, D[nn][3] + b1);
        }
    }
}

// ---------------------------------------------------------------------------
// Tensor-core Mahalanobis v3: s-outer / tiles-inner mainloop.
// One block per n, 128 thr. Warp w owns j-tiles {w, w+4, w+8} (+12 for w==0).
// Per k-step s: A fragments loaded ONCE (8 LDS), then 16 independent MMAs
// across 8 (tile, m-tile) accumulators -> latency hidden by issue breadth.
// Dyn smem floats: ICs[0..10400) | DmT[10400..14560)   (58240 B)
// ---------------------------------------------------------------------------
extern __shared__ float s_mh[];
__global__ __launch_bounds__(128) void maha_kernel(const float* __restrict__ ic) {
    float* ICs = s_mh;                 // [104][100]
    float* DmT = s_mh + 10400;         // [104][40] (cols 0..31 used)
    __shared__ float dists[BB];
    __shared__ __align__(8) unsigned long long mbar_sto[5];

    const int n = blockIdx.x;
    const int tid = threadIdx.x;
    const int w = tid >> 5, lane = tid & 31;
    const int g = lane >> 2, tig = lane & 3;

    unsigned int mb0 = (unsigned int)__cvta_generic_to_shared(&mbar_sto[0]);
    unsigned int icsh = (unsigned int)__cvta_generic_to_shared(ICs);
    const float* icn = ic + (size_t)n * (DP * DP);

    if (tid == 0) {
#pragma unroll
        for (int k = 0; k < 5; k++) mbar_init(mb0 + 8 * k, 1);
        asm volatile("fence.proxy.async.shared::cta;" ::: "memory");
#pragma unroll
        for (int k = 0; k < 5; k++) {
            mbar_expect_tx(mb0 + 8 * k, 8000);
            bulk_g2s(icsh + k * 8000, icn + k * 2000, 8000, mb0 + 8 * k);
        }
    }

    for (int i = tid; i < 400; i += 128) ICs[10000 + i] = 0.f;
    DmT[(100 + (tid >> 5)) * 40 + (tid & 31)] = 0.f;
    if (tid < BB) dists[tid] = 0.f;

    const int yo = n >> 6, xo = n & 63;
    float yin = (yo + 0.5f) * 0.5f - 0.5f;
    float xin = (xo + 0.5f) * 0.5f - 0.5f;
    int y0 = (int)floorf(yin), x0 = (int)floorf(xin);
    float fy = yin - (float)y0, fx = xin - (float)x0;
    int y0c = max(y0, 0), y1c = min(y0 + 1, HWI - 1);
    int x0c = max(x0, 0), x1c = min(x0 + 1, HWI - 1);
    float w00 = (1.f - fy) * (1.f - fx), w01 = (1.f - fy) * fx;
    float w10 = fy * (1.f - fx),         w11 = fy * fx;
    int p00 = y0c * HWI + x0c, p01 = y0c * HWI + x1c;
    int p10 = y1c * HWI + x0c, p11 = y1c * HWI + x1c;

    const float* mt = g_meanT + (size_t)n * DP;
    for (int idx = tid; idx < 800; idx += 128) {
        int b = idx / 25;
        int q = idx - b * 25;
        int c = q * 4;
        const float* P = g_proj + (size_t)b * PIN * DP;
        float4 t00 = *(const float4*)&P[p00 * DP + c];
        float4 t01 = *(const float4*)&P[p01 * DP + c];
        float4 t10 = *(const float4*)&P[p10 * DP + c];
        float4 t11 = *(const float4*)&P[p11 * DP + c];
        float4 m4 = *(const float4*)&mt[c];
        float v0 = w00 * t00.x + w01 * t01.x + w10 * t10.x + w11 * t11.x - m4.x;
        float v1 = w00 * t00.y + w01 * t01.y + w10 * t10.y + w11 * t11.y - m4.y;
        float v2 = w00 * t00.z + w01 * t01.z + w10 * t10.z + w11 * t11.z - m4.z;
        float v3 = w00 * t00.w + w01 * t01.w + w10 * t10.w + w11 * t11.w - m4.w;
        unsigned r0, r1, r2, r3;
        asm("cvt.rna.tf32.f32 %0, %1;" : "=r"(r0) : "f"(v0));
        asm("cvt.rna.tf32.f32 %0, %1;" : "=r"(r1) : "f"(v1));
        asm("cvt.rna.tf32.f32 %0, %1;" : "=r"(r2) : "f"(v2));
        asm("cvt.rna.tf32.f32 %0, %1;" : "=r"(r3) : "f"(v3));
        DmT[(c + 0) * 40 + b] = __uint_as_float(r0);
        DmT[(c + 1) * 40 + b] = __uint_as_float(r1);
        DmT[(c + 2) * 40 + b] = __uint_as_float(r2);
        DmT[(c + 3) * 40 + b] = __uint_as_float(r3);
    }
    __syncthreads();

    // wait for the full IC tile (block-level pipelining hides this across
    // the 3 resident blocks per SM)
#pragma unroll
    for (int k = 0; k < 5; k++) mbar_wait(mb0 + 8 * k, 0);

    const bool has4 = (w == 0);
    float d[4][2][4];
#pragma unroll
    for (int ti = 0; ti < 4; ti++)
#pragma unroll
        for (int m = 0; m < 2; m++)
#pragma unroll
            for (int q = 0; q < 4; q++) d[ti][m][q] = 0.f;

#pragma unroll
    for (int s = 0; s < 13; s++) {
        const int k0 = 8 * s;
        unsigned a0[4], a1[4];
        a0[0] = __float_as_uint(DmT[(k0 + tig) * 40 + g]);
        a0[1] = __float_as_uint(DmT[(k0 + tig) * 40 + g + 8]);
        a0[2] = __float_as_uint(DmT[(k0 + tig + 4) * 40 + g]);
        a0[3] = __float_as_uint(DmT[(k0 + tig + 4) * 40 + g + 8]);
        a1[0] = __float_as_uint(DmT[(k0 + tig) * 40 + 16 + g]);
        a1[1] = __float_as_uint(DmT[(k0 + tig) * 40 + 24 + g]);
        a1[2] = __float_as_uint(DmT[(k0 + tig + 4) * 40 + 16 + g]);
        a1[3] = __float_as_uint(DmT[(k0 + tig + 4) * 40 + 24 + g]);

#pragma unroll
        for (int ti = 0; ti < 4; ti++) {
            if (ti == 3 && !has4) continue;
            const int j0 = 8 * (w + 4 * ti);
            float braw0 = ICs[(j0 + g) * DP + k0 + tig];
            float braw1 = (s < 12) ? ICs[(j0 + g) * DP + k0 + tig + 4] : 0.f;
            unsigned bh[2], bl[2];
            bh[0] = __float_as_uint(braw0) & 0xFFFFE000u;
            bh[1] = __float_as_uint(braw1) & 0xFFFFE000u;
            bl[0] = __float_as_uint(braw0 - __uint_as_float(bh[0]));
            bl[1] = __float_as_uint(braw1 - __uint_as_float(bh[1]));
            mma8(d[ti][0], a0, bh);
            mma8(d[ti][1], a1, bh);
            mma8(d[ti][0], a0, bl);
            mma8(d[ti][1], a1, bl);
        }
    }

    float accd[4] = {0.f, 0.f, 0.f, 0.f};
#pragma unroll
    for (int ti = 0; ti < 4; ti++) {
        if (ti == 3 && !has4) continue;
        const int j0 = 8 * (w + 4 * ti);
        const float* wj0 = &DmT[(j0 + 2 * tig) * 40];
        const float* wj1 = &DmT[(j0 + 2 * tig + 1) * 40];
        accd[0] += d[ti][0][0] * wj0[g]      + d[ti][0][1] * wj1[g];
        accd[1] += d[ti][0][2] * wj0[g + 8]  + d[ti][0][3] * wj1[g + 8];
        accd[2] += d[ti][1][0] * wj0[16 + g] + d[ti][1][1] * wj1[16 + g];
        accd[3] += d[ti][1][2] * wj0[24 + g] + d[ti][1][3] * wj1[24 + g];
    }

    atomicAdd(&dists[g], accd[0]);
    atomicAdd(&dists[g + 8], accd[1]);
    atomicAdd(&dists[16 + g], accd[2]);
    atomicAdd(&dists[24 + g], accd[3]);
    __syncthreads();
    if (tid < BB) g_dist[(size_t)tid * NPOS + n] = dists[tid];
}

// ---------------------------------------------------------------------------
__global__ void upsample_kernel(const float* __restrict__ nmin_p,
                                const float* __restrict__ nmax_p,
                                float* __restrict__ out) {
    const int b = blockIdx.y;
    const int i = blockIdx.x * blockDim.x + threadIdx.x;
    const int yo = i >> 6;
    const int xb = (i & 63) * 4;

    float yin = (yo + 0.5f) * 0.25f - 0.5f;
    int y0 = (int)floorf(yin);
    float fy = yin - (float)y0;
    int y0c = max(y0, 0), y1c = min(y0 + 1, HWF - 1);

    const float* dn = g_dist + (size_t)b * NPOS;
    const float* r0 = dn + y0c * HWF;
    const float* r1 = dn + y1c * HWF;
    float nmin = *nmin_p, nmax = *nmax_p;
    float inv = 1.f / (nmax - nmin + 1e-8f);

    float4 res;
    float* resp = (float*)&res;
#pragma unroll
    for (int k = 0; k < 4; k++) {
        int xo = xb + k;
        float xin = (xo + 0.5f) * 0.25f - 0.5f;
        int x0 = (int)floorf(xin);
        float fx = xin - (float)x0;
        int x0c = max(x0, 0), x1c = min(x0 + 1, HWF - 1);
        float v = (1.f - fy) * ((1.f - fx) * r0[x0c] + fx * r0[x1c])
                + fy * ((1.f - fx) * r1[x0c] + fx * r1[x1c]);
        resp[k] = (v - nmin) * inv;
    }
    *(float4*)&out[(size_t)b * (OHW * OHW) + yo * OHW + xb] = res;
}

// ---------------------------------------------------------------------------
extern "C" void kernel_launch(void* const* d_in, const int* in_sizes, int n_in,
                              void* d_out, int out_size) {
    (void)in_sizes; (void)n_in; (void)out_size;
    const float* combined = (const float*)d_in[0];
    const float* proj_w   = (const float*)d_in[1];
    const float* proj_b   = (const float*)d_in[2];
    const float* mean     = (const float*)d_in[3];
    const float* inv_cov  = (const float*)d_in[4];
    const float* nmin     = (const float*)d_in[5];
    const float* nmax     = (const float*)d_in[6];
    float* out = (float*)d_out;

    static int smem_set = 0;
    if (!smem_set) {
        cudaFuncSetAttribute(maha_kernel,
                             cudaFuncAttributeMaxDynamicSharedMemorySize,
                             58240);
        smem_set = 1;
    }

    prep_w_kernel<<<(DPAD * CC + 255) / 256, 256>>>(proj_w);
    prep_mean_kernel<<<dim3(NPOS / 32, 4), dim3(32, 8)>>>(mean);
    proj_kernel<<<dim3(16, BB), 256>>>(combined, proj_b);
    maha_kernel<<<NPOS, 128, 58240>>>(inv_cov);
    upsample_kernel<<<dim3(OHW * OHW / (256 * 4), BB), 256>>>(nmin, nmax, out);
}